// round 14
// baseline (speedup 1.0000x reference)
#include <cuda_runtime.h>
#include <cuda_fp16.h>
#include <math.h>
#include <stdint.h>

#define BB 32
#define SS 4096
#define HH 256
#define DD 512
#define MM (BB*SS)

#define CTX_CHUNKS 32

// ---- scratch (device globals; no allocation allowed) ----
__device__ float g_decf[BB*DD];                 // dec_feat (B,D)
__device__ float g_score[MM];                   // raw scores (B,S)
__device__ float g_ctx_part[CTX_CHUNKS*BB*DD];  // split-S context partials
__device__ __half g_WhHf[DD*DD];                // Wh pre-converted to fp16
__device__ __half g_encHf[(size_t)MM*DD];       // encoder fp16 copy (written by score kernel)

// ============================================================
// helpers
// ============================================================
__device__ __forceinline__ uint32_t smem_to_u32(const void* p) {
    uint32_t a;
    asm("{ .reg .u64 t; cvta.to.shared.u64 t, %1; cvt.u32.u64 %0, t; }" : "=r"(a) : "l"(p));
    return a;
}

#define CP_ASYNC16(dst, src) \
    asm volatile("cp.async.cg.shared.global [%0], [%1], 16;" :: "r"(dst), "l"(src) : "memory")
#define CP_COMMIT() asm volatile("cp.async.commit_group;" ::: "memory")
#define CP_WAIT(n)  asm volatile("cp.async.wait_group %0;" :: "n"(n) : "memory")

__device__ __forceinline__ void ldsm_x4(uint32_t r[4], uint32_t addr) {
    asm volatile("ldmatrix.sync.aligned.m8n8.x4.shared.b16 {%0,%1,%2,%3}, [%4];"
        : "=r"(r[0]), "=r"(r[1]), "=r"(r[2]), "=r"(r[3]) : "r"(addr));
}

// fp16-accumulate HMMA: D,C are 2x b32 regs (half2 pairs {c0,c1},{c2,c3})
__device__ __forceinline__ void mma_f16h(uint32_t c[2], const uint32_t a[4], const uint32_t* b) {
    asm volatile(
        "mma.sync.aligned.m16n8k16.row.col.f16.f16.f16.f16 "
        "{%0,%1},{%2,%3,%4,%5},{%6,%7},{%0,%1};"
        : "+r"(c[0]), "+r"(c[1])
        : "r"(a[0]), "r"(a[1]), "r"(a[2]), "r"(a[3]), "r"(b[0]), "r"(b[1]));
}

__device__ __forceinline__ uint4 pack8h(float4 a, float4 b) {
    __half2 p0 = __floats2half2_rn(a.x, a.y);
    __half2 p1 = __floats2half2_rn(a.z, a.w);
    __half2 p2 = __floats2half2_rn(b.x, b.y);
    __half2 p3 = __floats2half2_rn(b.z, b.w);
    uint4 r;
    r.x = *(uint32_t*)&p0; r.y = *(uint32_t*)&p1;
    r.z = *(uint32_t*)&p2; r.w = *(uint32_t*)&p3;
    return r;
}

// SMEM layout (bytes)
#define SM_A    0
#define SM_W    131072
#define SM_PAR  196608
#define SM_TOTAL 203776

// ============================================================
// K0: merged prep.
// blocks [0,128): convert Wh (512x512 f32) -> fp16 row-major [n][k]
// blocks [128,256): dec_feat[b,n] = sum_k s_t[b,k]*Ws[n,k] + Ws_b[n]
// ============================================================
__global__ void __launch_bounds__(256) prep_kernel(
    const float* __restrict__ Wh,
    const float* __restrict__ h, const float* __restrict__ c,
    const float* __restrict__ Ws, const float* __restrict__ Wsb)
{
    if (blockIdx.x < 128) {
        int i = (blockIdx.x * 256 + threadIdx.x) * 8;
        float4 v0 = *(const float4*)(Wh + i);
        float4 v1 = *(const float4*)(Wh + i + 4);
        *(uint4*)(&g_WhHf[i]) = pack8h(v0, v1);
    } else {
        int blk = blockIdx.x - 128;          // 0..127
        int b = blk >> 2, quarter = blk & 3;
        __shared__ float st[DD];
        for (int p = threadIdx.x; p < DD; p += 256)
            st[p] = (p < HH) ? h[b*HH + p] : c[b*HH + (p - HH)];
        __syncthreads();
        if (threadIdx.x < 128) {
            int n = quarter * 128 + threadIdx.x;
            float acc = Wsb[n];
            const float4* wrow = (const float4*)(Ws + (size_t)n * DD);
#pragma unroll 8
            for (int k4 = 0; k4 < DD/4; ++k4) {
                float4 w = wrow[k4];
                acc += w.x * st[k4*4+0] + w.y * st[k4*4+1]
                     + w.z * st[k4*4+2] + w.w * st[k4*4+3];
            }
            g_decf[b*DD + n] = acc;
        }
    }
}

// ============================================================
// K1: fused score GEMM, fp16 mma.sync.m16n8k16 (fp16 accumulate,
// promoted to fp32 every K=128 chunk) + ldmatrix + cp.async.
// fp16 encoder copy STG issued AFTER the mainloop (drains under
// the epilogue + next CTA's prologue).
// 512 threads / 16 warps (4M x 4N), grid 1024.
// ============================================================
__global__ void __launch_bounds__(512) score_f16_kernel(
    const float* __restrict__ enc, const float* __restrict__ cov,
    const float* __restrict__ wc, const float* __restrict__ vw)
{
    extern __shared__ __align__(1024) char smem[];
    const uint32_t sbase = smem_to_u32(smem);
    const int tid = threadIdx.x;
    const int lane = tid & 31, wid = tid >> 5;
    const int warpM = wid >> 2, warpN = wid & 3;   // 4 x 4 warp grid
    const int g = lane >> 2, q = lane & 3;
    const int row0 = blockIdx.x * 128;
    const int b = row0 >> 12;

    float* sDecf  = (float*)(smem + SM_PAR);
    float* sWc    = sDecf + 512;
    float* sV     = sWc + 512;
    float* sCov   = sV + 512;
    float* sScore = sCov + 128;

    // --- prefetch W tile (nt=0,kc=0) into buffer 0 ---
    {
        const char* src = (const char*)(g_WhHf);
#pragma unroll
        for (int i = 0; i < 4; ++i) {
            int cix = tid + i * 512;                        // 0..2047 16B chunks
            int n = cix >> 4, ch = cix & 15;
            uint32_t dst = sbase + SM_W + n*256 + (((uint32_t)(ch ^ (n & 7))) << 4);
            CP_ASYNC16(dst, src + ((size_t)n*DD + ch*8) * 2);
        }
        CP_COMMIT();
    }

    // --- load A slab: 128 rows x 512 f32 -> fp16, swizzled smem ---
#pragma unroll
    for (int i = 0; i < 16; ++i) {
        int cix = tid + i * 512;                            // 0..8191 chunks
        int row = cix >> 6, ch = cix & 63;
        const float4* src = (const float4*)(enc + (size_t)(row0 + row)*DD + ch*8);
        uint4 v = pack8h(src[0], src[1]);
        *(uint4*)(smem + SM_A + row*1024 + (((uint32_t)(ch ^ (row & 7))) << 4)) = v;
    }
    // --- params ---
    if (tid < 512) {
        sDecf[tid] = g_decf[b*DD + tid];
        sWc[tid]   = wc[tid];
        sV[tid]    = vw[tid];
    }
    if (tid < 128) { sCov[tid] = cov[row0 + tid]; sScore[tid] = 0.f; }
    __syncthreads();

    float rs[2][2];
    rs[0][0] = rs[0][1] = rs[1][0] = rs[1][1] = 0.f;

    // lane-dependent addressing pieces
    const int aLaneRow = lane & 15;
    const int aChunkOff = lane >> 4;
    const int bLaneRowOff = ((lane & 16) ? 8 : 0) + (lane & 7);
    const int bChunkOff = (lane >> 3) & 1;

    uint32_t aRowBase[2];
    int aRowMask[2];
#pragma unroll
    for (int mi = 0; mi < 2; ++mi) {
        int row = warpM*32 + mi*16 + aLaneRow;
        aRowBase[mi] = sbase + SM_A + row*1024;
        aRowMask[mi] = row & 7;
    }
    uint32_t bRowBase[2];
    int bRowMask[2];
#pragma unroll
    for (int nj = 0; nj < 2; ++nj) {
        int nrow = warpN*32 + nj*16 + bLaneRowOff;
        bRowBase[nj] = nrow*256;
        bRowMask[nj] = nrow & 7;
    }

    for (int nt = 0; nt < 4; ++nt) {
        float acc[2][4][4];
#pragma unroll
        for (int mi = 0; mi < 2; ++mi)
#pragma unroll
            for (int ni = 0; ni < 4; ++ni)
#pragma unroll
                for (int j = 0; j < 4; ++j) acc[mi][ni][j] = 0.f;

        for (int kc = 0; kc < 4; ++kc) {
            const int idx = nt*4 + kc;
            // prefetch next W tile into the other buffer
            if (idx < 15) {
                const int nx = idx + 1;
                const int nt2 = nx >> 2, kc2 = nx & 3, buf2 = nx & 1;
                const char* src = (const char*)(g_WhHf + (size_t)(nt2*128)*DD + kc2*128);
#pragma unroll
                for (int i = 0; i < 4; ++i) {
                    int cix = tid + i * 512;
                    int n = cix >> 4, ch = cix & 15;
                    uint32_t dst = sbase + SM_W + buf2*32768 + n*256
                                 + (((uint32_t)(ch ^ (n & 7))) << 4);
                    CP_ASYNC16(dst, src + ((size_t)n*DD + ch*8) * 2);
                }
                CP_COMMIT();
                CP_WAIT(1);
            } else {
                CP_WAIT(0);
            }
            __syncthreads();

            const uint32_t wBase = sbase + SM_W + (idx & 1)*32768;

            // fp16 accumulators for this K=128 chunk
            uint32_t acch[2][4][2];
#pragma unroll
            for (int mi = 0; mi < 2; ++mi)
#pragma unroll
                for (int ni = 0; ni < 4; ++ni) {
                    acch[mi][ni][0] = 0u; acch[mi][ni][1] = 0u;
                }

#pragma unroll
            for (int k16 = 0; k16 < 8; ++k16) {
                const int ck  = kc*16 + k16*2 + aChunkOff;
                const int ck2 = k16*2 + bChunkOff;

                uint32_t a[2][4];
#pragma unroll
                for (int mi = 0; mi < 2; ++mi)
                    ldsm_x4(a[mi], aRowBase[mi] + (((uint32_t)(ck ^ aRowMask[mi])) << 4));
                uint32_t bf[2][4];
#pragma unroll
                for (int nj = 0; nj < 2; ++nj)
                    ldsm_x4(bf[nj], wBase + bRowBase[nj] + (((uint32_t)(ck2 ^ bRowMask[nj])) << 4));
#pragma unroll
                for (int mi = 0; mi < 2; ++mi)
#pragma unroll
                    for (int ni = 0; ni < 4; ++ni)
                        mma_f16h(acch[mi][ni], a[mi], &bf[ni >> 1][(ni & 1) * 2]);
            }

            // promote chunk partials to fp32
#pragma unroll
            for (int mi = 0; mi < 2; ++mi)
#pragma unroll
                for (int ni = 0; ni < 4; ++ni) {
                    float2 lo = __half22float2(*(__half2*)&acch[mi][ni][0]);
                    float2 hi = __half22float2(*(__half2*)&acch[mi][ni][1]);
                    acc[mi][ni][0] += lo.x; acc[mi][ni][1] += lo.y;
                    acc[mi][ni][2] += hi.x; acc[mi][ni][3] += hi.y;
                }
            __syncthreads();
        }

        // epilogue for this n-tile
        const int colbase = nt*128 + warpN*32;
#pragma unroll
        for (int mi = 0; mi < 2; ++mi) {
            const int rowg = warpM*32 + mi*16 + g;
            const float cv0 = sCov[rowg], cv1 = sCov[rowg + 8];
#pragma unroll
            for (int ni = 0; ni < 4; ++ni) {
#pragma unroll
                for (int half = 0; half < 2; ++half) {
#pragma unroll
                    for (int jj = 0; jj < 2; ++jj) {
                        const int col = colbase + ni*8 + q*2 + jj;
                        float arg = acc[mi][ni][half*2 + jj]
                                  + sDecf[col] + (half ? cv1 : cv0) * sWc[col];
                        float t;
                        asm("tanh.approx.f32 %0, %1;" : "=f"(t) : "f"(arg));
                        rs[mi][half] += t * sV[col];
                    }
                }
            }
        }
    }

    // --- emit fp16 encoder copy from the resident A slab; the STG drain
    // overlaps the reduction below and the next CTA's prologue ---
#pragma unroll
    for (int i = 0; i < 16; ++i) {
        int cix = tid + i * 512;
        int row = cix >> 6, ch = cix & 63;
        uint4 v = *(const uint4*)(smem + SM_A + row*1024
                      + (((uint32_t)(ch ^ (row & 7))) << 4));
        *(uint4*)(&g_encHf[(size_t)(row0 + row)*DD + ch*8]) = v;
    }

    // reduce over the 4 column-lanes (q) per row, then across warpN via smem
#pragma unroll
    for (int mi = 0; mi < 2; ++mi)
#pragma unroll
        for (int half = 0; half < 2; ++half) {
            float v = rs[mi][half];
            v += __shfl_xor_sync(0xffffffffu, v, 1);
            v += __shfl_xor_sync(0xffffffffu, v, 2);
            if (q == 0)
                atomicAdd(&sScore[warpM*32 + mi*16 + half*8 + g], v);
        }
    __syncthreads();
    if (tid < 128) g_score[row0 + tid] = sScore[tid];
}

// ============================================================
// K2: masked softmax + renormalize + coverage update, per batch.
// 1024 threads, warp-shuffle reductions.
// ============================================================
__global__ void __launch_bounds__(1024) softmax_kernel(
    const float* __restrict__ mask, const float* __restrict__ cov,
    float* __restrict__ attn_out, float* __restrict__ covnew_out)
{
    const int b = blockIdx.x, tid = threadIdx.x;
    const int lane = tid & 31, wrp = tid >> 5;
    __shared__ float red[32];
    float loc[4];
    float mx = -1e30f;
#pragma unroll
    for (int i = 0; i < 4; ++i) {
        loc[i] = g_score[b*SS + tid + i*1024];
        mx = fmaxf(mx, loc[i]);
    }
#pragma unroll
    for (int o = 16; o > 0; o >>= 1) mx = fmaxf(mx, __shfl_xor_sync(0xffffffffu, mx, o));
    if (lane == 0) red[wrp] = mx;
    __syncthreads();
    {
        float v = red[lane];
#pragma unroll
        for (int o = 16; o > 0; o >>= 1) v = fmaxf(v, __shfl_xor_sync(0xffffffffu, v, o));
        mx = v;
    }

    float sum = 0.f;
#pragma unroll
    for (int i = 0; i < 4; ++i) {
        loc[i] = expf(loc[i] - mx) * mask[b*SS + tid + i*1024];
        sum += loc[i];
    }
#pragma unroll
    for (int o = 16; o > 0; o >>= 1) sum += __shfl_xor_sync(0xffffffffu, sum, o);
    __syncthreads();
    if (lane == 0) red[wrp] = sum;
    __syncthreads();
    {
        float v = red[lane];
#pragma unroll
        for (int o = 16; o > 0; o >>= 1) v += __shfl_xor_sync(0xffffffffu, v, o);
        sum = v;
    }
    const float inv = 1.f / sum;
#pragma unroll
    for (int i = 0; i < 4; ++i) {
        int idx = b*SS + tid + i*1024;
        float a = loc[i] * inv;
        attn_out[idx]   = a;
        covnew_out[idx] = cov[idx] + a;
    }
}

// ============================================================
// K3: context partials from the fp16 encoder copy.
// grid (32 s-chunks, B), 512 threads.
// ============================================================
__global__ void __launch_bounds__(512) context_kernel(
    const float* __restrict__ attn)
{
    const int chunk = blockIdx.x, b = blockIdx.y, tid = threadIdx.x;
    __shared__ float sAttn[128];
    __shared__ float sAcc[512*8];   // 16 KB
    if (tid < 128) sAttn[tid] = attn[b*SS + chunk*128 + tid];
    __syncthreads();
    const int dt = tid & 63, sg = tid >> 6;
    float acc[8];
#pragma unroll
    for (int j = 0; j < 8; ++j) acc[j] = 0.f;
    const size_t base = ((size_t)(b*SS + chunk*128))*DD + dt*8;
#pragma unroll 8
    for (int s = sg; s < 128; s += 8) {
        float a = sAttn[s];
        uint4 hv = *(const uint4*)(&g_encHf[base + (size_t)s*DD]);
        float2 f0 = __half22float2(*(__half2*)&hv.x);
        float2 f1 = __half22float2(*(__half2*)&hv.y);
        float2 f2 = __half22float2(*(__half2*)&hv.z);
        float2 f3 = __half22float2(*(__half2*)&hv.w);
        acc[0] += a*f0.x; acc[1] += a*f0.y;
        acc[2] += a*f1.x; acc[3] += a*f1.y;
        acc[4] += a*f2.x; acc[5] += a*f2.y;
        acc[6] += a*f3.x; acc[7] += a*f3.y;
    }
#pragma unroll
    for (int j = 0; j < 8; ++j) sAcc[tid*8 + j] = acc[j];
    __syncthreads();
    if (sg == 0) {
        float r[8];
#pragma unroll
        for (int j = 0; j < 8; ++j) r[j] = sAcc[dt*8 + j];
#pragma unroll
        for (int gr = 1; gr < 8; ++gr)
#pragma unroll
            for (int j = 0; j < 8; ++j) r[j] += sAcc[(gr*64 + dt)*8 + j];
        float* dst = &g_ctx_part[((size_t)chunk*BB + b)*DD + dt*8];
#pragma unroll
        for (int j = 0; j < 8; ++j) dst[j] = r[j];
    }
}

// K4: reduce the s-chunk partials -> context output (deterministic)
__global__ void __launch_bounds__(1024) ctx_reduce_kernel(float* __restrict__ out_ctx)
{
    int i = blockIdx.x * 1024 + threadIdx.x;  // 0..16383
    float s = 0.f;
#pragma unroll
    for (int c = 0; c < CTX_CHUNKS; ++c) s += g_ctx_part[c*(BB*DD) + i];
    out_ctx[i] = s;
}

// ============================================================
extern "C" void kernel_launch(void* const* d_in, const int* in_sizes, int n_in,
                              void* d_out, int out_size)
{
    const float* enc  = (const float*)d_in[0];
    const float* h    = (const float*)d_in[1];
    const float* c    = (const float*)d_in[2];
    const float* mask = (const float*)d_in[3];
    const float* cov  = (const float*)d_in[4];
    const float* Wh   = (const float*)d_in[5];
    const float* Ws   = (const float*)d_in[6];
    const float* Wsb  = (const float*)d_in[7];
    const float* wc   = (const float*)d_in[8];
    const float* vw   = (const float*)d_in[9];

    float* out      = (float*)d_out;
    float* out_ctx  = out;                 // (B,D)   16384
    float* out_attn = out + BB*DD;         // (B,S)   131072
    float* out_cov  = out_attn + BB*SS;    // (B,S)   131072

    cudaFuncSetAttribute(score_f16_kernel,
                         cudaFuncAttributeMaxDynamicSharedMemorySize, SM_TOTAL);

    prep_kernel<<<256, 256>>>(Wh, h, c, Ws, Wsb);
    score_f16_kernel<<<MM/128, 512, SM_TOTAL>>>(enc, cov, wc, vw);
    softmax_kernel<<<BB, 1024>>>(mask, cov, out_attn, out_cov);
    context_kernel<<<dim3(CTX_CHUNKS, BB), 512>>>(out_attn);
    ctx_reduce_kernel<<<(BB*DD)/1024, 1024>>>(out_ctx);
}

// round 16
// speedup vs baseline: 1.2187x; 1.2187x over previous
#include <cuda_runtime.h>
#include <cuda_fp16.h>
#include <math.h>
#include <stdint.h>

#define BB 32
#define SS 4096
#define HH 256
#define DD 512
#define MM (BB*SS)

#define CTX_CHUNKS 32   // one partial per score CTA (128 rows each)

// ---- scratch (device globals; no allocation allowed) ----
__device__ float g_decf[BB*DD];                 // dec_feat (B,D)
__device__ float g_score[MM];                   // raw scores (B,S)
__device__ float g_ctx_part[CTX_CHUNKS*BB*DD];  // unnormalized context partials
__device__ float g_ssum[BB];                    // softmax masked sum per batch
__device__ __half g_WhHf[DD*DD];                // Wh pre-converted to fp16

// ============================================================
// helpers
// ============================================================
__device__ __forceinline__ uint32_t smem_to_u32(const void* p) {
    uint32_t a;
    asm("{ .reg .u64 t; cvta.to.shared.u64 t, %1; cvt.u32.u64 %0, t; }" : "=r"(a) : "l"(p));
    return a;
}

#define CP_ASYNC16(dst, src) \
    asm volatile("cp.async.cg.shared.global [%0], [%1], 16;" :: "r"(dst), "l"(src) : "memory")
#define CP_COMMIT() asm volatile("cp.async.commit_group;" ::: "memory")
#define CP_WAIT(n)  asm volatile("cp.async.wait_group %0;" :: "n"(n) : "memory")

__device__ __forceinline__ void ldsm_x4(uint32_t r[4], uint32_t addr) {
    asm volatile("ldmatrix.sync.aligned.m8n8.x4.shared.b16 {%0,%1,%2,%3}, [%4];"
        : "=r"(r[0]), "=r"(r[1]), "=r"(r[2]), "=r"(r[3]) : "r"(addr));
}

// fp32-accumulate fp16 MMA (the proven fastest config)
__device__ __forceinline__ void mma_f16(float c[4], const uint32_t a[4], const uint32_t* b) {
    asm volatile(
        "mma.sync.aligned.m16n8k16.row.col.f32.f16.f16.f32 "
        "{%0,%1,%2,%3},{%4,%5,%6,%7},{%8,%9},{%0,%1,%2,%3};"
        : "+f"(c[0]), "+f"(c[1]), "+f"(c[2]), "+f"(c[3])
        : "r"(a[0]), "r"(a[1]), "r"(a[2]), "r"(a[3]), "r"(b[0]), "r"(b[1]));
}

__device__ __forceinline__ uint4 pack8h(float4 a, float4 b) {
    __half2 p0 = __floats2half2_rn(a.x, a.y);
    __half2 p1 = __floats2half2_rn(a.z, a.w);
    __half2 p2 = __floats2half2_rn(b.x, b.y);
    __half2 p3 = __floats2half2_rn(b.z, b.w);
    uint4 r;
    r.x = *(uint32_t*)&p0; r.y = *(uint32_t*)&p1;
    r.z = *(uint32_t*)&p2; r.w = *(uint32_t*)&p3;
    return r;
}

// SMEM layout (bytes)
#define SM_A    0            // 128 x 1024B fp16 A slab (swizzled)
#define SM_W    131072       // 2 x 32KB W double buffer; reused as sAcc (16KB) in epilogue
#define SM_PAR  196608       // decf[512] wc[512] v[512] cov[128] score[128] floats
#define SM_TOTAL 203776

// ============================================================
// K0: merged prep.
// blocks [0,128): convert Wh (512x512 f32) -> fp16 row-major [n][k]
// blocks [128,256): dec_feat[b,n] = sum_k s_t[b,k]*Ws[n,k] + Ws_b[n]
// ============================================================
__global__ void __launch_bounds__(256) prep_kernel(
    const float* __restrict__ Wh,
    const float* __restrict__ h, const float* __restrict__ c,
    const float* __restrict__ Ws, const float* __restrict__ Wsb)
{
    if (blockIdx.x < 128) {
        int i = (blockIdx.x * 256 + threadIdx.x) * 8;
        float4 v0 = *(const float4*)(Wh + i);
        float4 v1 = *(const float4*)(Wh + i + 4);
        *(uint4*)(&g_WhHf[i]) = pack8h(v0, v1);
    } else {
        int blk = blockIdx.x - 128;          // 0..127
        int b = blk >> 2, quarter = blk & 3;
        __shared__ float st[DD];
        for (int p = threadIdx.x; p < DD; p += 256)
            st[p] = (p < HH) ? h[b*HH + p] : c[b*HH + (p - HH)];
        __syncthreads();
        if (threadIdx.x < 128) {
            int n = quarter * 128 + threadIdx.x;
            float acc = Wsb[n];
            const float4* wrow = (const float4*)(Ws + (size_t)n * DD);
#pragma unroll 8
            for (int k4 = 0; k4 < DD/4; ++k4) {
                float4 w = wrow[k4];
                acc += w.x * st[k4*4+0] + w.y * st[k4*4+1]
                     + w.z * st[k4*4+2] + w.w * st[k4*4+3];
            }
            g_decf[b*DD + n] = acc;
        }
    }
}

// ============================================================
// K1: fused score GEMM + context partials.
// fp16 mma.sync.m16n8k16 (f32 accum) + ldmatrix + cp.async.
// After the GEMM reduces scores, the CTA computes
//   ctx_part[d] = sum_s exp(score_s)*mask_s*enc[s,d]
// from its resident A slab (no second encoder pass needed).
// 512 threads / 16 warps (4M x 4N), grid 1024.
// ============================================================
__global__ void __launch_bounds__(512) score_f16_kernel(
    const float* __restrict__ enc, const float* __restrict__ cov,
    const float* __restrict__ wc, const float* __restrict__ vw,
    const float* __restrict__ mask)
{
    extern __shared__ __align__(1024) char smem[];
    const uint32_t sbase = smem_to_u32(smem);
    const int tid = threadIdx.x;
    const int lane = tid & 31, wid = tid >> 5;
    const int warpM = wid >> 2, warpN = wid & 3;   // 4 x 4 warp grid
    const int g = lane >> 2, q = lane & 3;
    const int row0 = blockIdx.x * 128;
    const int b = row0 >> 12;
    const int chunk = blockIdx.x & 31;

    float* sDecf  = (float*)(smem + SM_PAR);
    float* sWc    = sDecf + 512;
    float* sV     = sWc + 512;
    float* sCov   = sV + 512;      // reused as weights after nt-epilogues
    float* sScore = sCov + 128;

    // --- prefetch W tile (nt=0,kc=0) into buffer 0 ---
    {
        const char* src = (const char*)(g_WhHf);
#pragma unroll
        for (int i = 0; i < 4; ++i) {
            int cix = tid + i * 512;                        // 0..2047 16B chunks
            int n = cix >> 4, ch = cix & 15;
            uint32_t dst = sbase + SM_W + n*256 + (((uint32_t)(ch ^ (n & 7))) << 4);
            CP_ASYNC16(dst, src + ((size_t)n*DD + ch*8) * 2);
        }
        CP_COMMIT();
    }

    // --- load A slab: 128 rows x 512 f32 -> fp16, swizzled smem ---
#pragma unroll
    for (int i = 0; i < 16; ++i) {
        int cix = tid + i * 512;                            // 0..8191 chunks
        int row = cix >> 6, ch = cix & 63;
        const float4* src = (const float4*)(enc + (size_t)(row0 + row)*DD + ch*8);
        uint4 v = pack8h(src[0], src[1]);
        *(uint4*)(smem + SM_A + row*1024 + (((uint32_t)(ch ^ (row & 7))) << 4)) = v;
    }
    // --- params ---
    if (tid < 512) {
        sDecf[tid] = g_decf[b*DD + tid];
        sWc[tid]   = wc[tid];
        sV[tid]    = vw[tid];
    }
    if (tid < 128) { sCov[tid] = cov[row0 + tid]; sScore[tid] = 0.f; }
    __syncthreads();

    float rs[2][2];
    rs[0][0] = rs[0][1] = rs[1][0] = rs[1][1] = 0.f;

    // lane-dependent addressing pieces
    const int aLaneRow = lane & 15;
    const int aChunkOff = lane >> 4;
    const int bLaneRowOff = ((lane & 16) ? 8 : 0) + (lane & 7);
    const int bChunkOff = (lane >> 3) & 1;

    uint32_t aRowBase[2];
    int aRowMask[2];
#pragma unroll
    for (int mi = 0; mi < 2; ++mi) {
        int row = warpM*32 + mi*16 + aLaneRow;
        aRowBase[mi] = sbase + SM_A + row*1024;
        aRowMask[mi] = row & 7;
    }
    uint32_t bRowBase[2];
    int bRowMask[2];
#pragma unroll
    for (int nj = 0; nj < 2; ++nj) {
        int nrow = warpN*32 + nj*16 + bLaneRowOff;
        bRowBase[nj] = nrow*256;
        bRowMask[nj] = nrow & 7;
    }

    for (int nt = 0; nt < 4; ++nt) {
        float acc[2][4][4];
#pragma unroll
        for (int mi = 0; mi < 2; ++mi)
#pragma unroll
            for (int ni = 0; ni < 4; ++ni)
#pragma unroll
                for (int j = 0; j < 4; ++j) acc[mi][ni][j] = 0.f;

        for (int kc = 0; kc < 4; ++kc) {
            const int idx = nt*4 + kc;
            // prefetch next W tile into the other buffer
            if (idx < 15) {
                const int nx = idx + 1;
                const int nt2 = nx >> 2, kc2 = nx & 3, buf2 = nx & 1;
                const char* src = (const char*)(g_WhHf + (size_t)(nt2*128)*DD + kc2*128);
#pragma unroll
                for (int i = 0; i < 4; ++i) {
                    int cix = tid + i * 512;
                    int n = cix >> 4, ch = cix & 15;
                    uint32_t dst = sbase + SM_W + buf2*32768 + n*256
                                 + (((uint32_t)(ch ^ (n & 7))) << 4);
                    CP_ASYNC16(dst, src + ((size_t)n*DD + ch*8) * 2);
                }
                CP_COMMIT();
                CP_WAIT(1);
            } else {
                CP_WAIT(0);
            }
            __syncthreads();

            const uint32_t wBase = sbase + SM_W + (idx & 1)*32768;

#pragma unroll
            for (int k16 = 0; k16 < 8; ++k16) {
                const int ck  = kc*16 + k16*2 + aChunkOff;
                const int ck2 = k16*2 + bChunkOff;

                uint32_t a[2][4];
#pragma unroll
                for (int mi = 0; mi < 2; ++mi)
                    ldsm_x4(a[mi], aRowBase[mi] + (((uint32_t)(ck ^ aRowMask[mi])) << 4));
                uint32_t bf[2][4];
#pragma unroll
                for (int nj = 0; nj < 2; ++nj)
                    ldsm_x4(bf[nj], wBase + bRowBase[nj] + (((uint32_t)(ck2 ^ bRowMask[nj])) << 4));
#pragma unroll
                for (int mi = 0; mi < 2; ++mi)
#pragma unroll
                    for (int ni = 0; ni < 4; ++ni)
                        mma_f16(acc[mi][ni], a[mi], &bf[ni >> 1][(ni & 1) * 2]);
            }
            __syncthreads();
        }

        // epilogue for this n-tile
        const int colbase = nt*128 + warpN*32;
#pragma unroll
        for (int mi = 0; mi < 2; ++mi) {
            const int rowg = warpM*32 + mi*16 + g;
            const float cv0 = sCov[rowg], cv1 = sCov[rowg + 8];
#pragma unroll
            for (int ni = 0; ni < 4; ++ni) {
#pragma unroll
                for (int half = 0; half < 2; ++half) {
#pragma unroll
                    for (int jj = 0; jj < 2; ++jj) {
                        const int col = colbase + ni*8 + q*2 + jj;
                        float arg = acc[mi][ni][half*2 + jj]
                                  + sDecf[col] + (half ? cv1 : cv0) * sWc[col];
                        float t;
                        asm("tanh.approx.f32 %0, %1;" : "=f"(t) : "f"(arg));
                        rs[mi][half] += t * sV[col];
                    }
                }
            }
        }
    }

    // reduce over the 4 column-lanes (q) per row, then across warpN via smem
#pragma unroll
    for (int mi = 0; mi < 2; ++mi)
#pragma unroll
        for (int half = 0; half < 2; ++half) {
            float v = rs[mi][half];
            v += __shfl_xor_sync(0xffffffffu, v, 1);
            v += __shfl_xor_sync(0xffffffffu, v, 2);
            if (q == 0)
                atomicAdd(&sScore[warpM*32 + mi*16 + half*8 + g], v);
        }
    __syncthreads();

    if (tid < 128) {
        float sc = sScore[tid];
        g_score[row0 + tid] = sc;
        // unnormalized softmax weight (no max-shift: |score| <= ||v||_1, safe in f32)
        sCov[tid] = expf(sc) * mask[row0 + tid];   // sCov reused as weights
    }
    __syncthreads();

    // --- context partial from the resident A slab ---
    // ctx_part[d] = sum_{s=0..127} w[s] * A[s,d]
    {
        const int dt = tid & 63, sg = tid >> 6;    // 64 d-chunks x 8 row-groups
        float acc8[8];
#pragma unroll
        for (int j = 0; j < 8; ++j) acc8[j] = 0.f;
#pragma unroll 8
        for (int s = sg; s < 128; s += 8) {
            float w = sCov[s];
            uint4 hv = *(const uint4*)(smem + SM_A + s*1024
                          + (((uint32_t)(dt ^ (s & 7))) << 4));
            float2 f0 = __half22float2(*(__half2*)&hv.x);
            float2 f1 = __half22float2(*(__half2*)&hv.y);
            float2 f2 = __half22float2(*(__half2*)&hv.z);
            float2 f3 = __half22float2(*(__half2*)&hv.w);
            acc8[0] += w*f0.x; acc8[1] += w*f0.y;
            acc8[2] += w*f1.x; acc8[3] += w*f1.y;
            acc8[4] += w*f2.x; acc8[5] += w*f2.y;
            acc8[6] += w*f3.x; acc8[7] += w*f3.y;
        }
        float* sAcc = (float*)(smem + SM_W);       // W buffers are dead now
#pragma unroll
        for (int j = 0; j < 8; ++j) sAcc[tid*8 + j] = acc8[j];
        __syncthreads();
        if (sg == 0) {
            float r[8];
#pragma unroll
            for (int j = 0; j < 8; ++j) r[j] = sAcc[dt*8 + j];
#pragma unroll
            for (int gr = 1; gr < 8; ++gr)
#pragma unroll
                for (int j = 0; j < 8; ++j) r[j] += sAcc[(gr*64 + dt)*8 + j];
            float* dst = &g_ctx_part[((size_t)chunk*BB + b)*DD + dt*8];
#pragma unroll
            for (int j = 0; j < 8; ++j) dst[j] = r[j];
        }
    }
}

// ============================================================
// K2: masked softmax + renormalize + coverage update, per batch.
// Uses exp(score) with NO max-shift (consistent with ctx partials).
// Also stores the per-batch masked sum for ctx normalization.
// ============================================================
__global__ void __launch_bounds__(1024) softmax_kernel(
    const float* __restrict__ mask, const float* __restrict__ cov,
    float* __restrict__ attn_out, float* __restrict__ covnew_out)
{
    const int b = blockIdx.x, tid = threadIdx.x;
    const int lane = tid & 31, wrp = tid >> 5;
    __shared__ float red[32];
    float loc[4];
    float sum = 0.f;
#pragma unroll
    for (int i = 0; i < 4; ++i) {
        int idx = b*SS + tid + i*1024;
        loc[i] = expf(g_score[idx]) * mask[idx];
        sum += loc[i];
    }
#pragma unroll
    for (int o = 16; o > 0; o >>= 1) sum += __shfl_xor_sync(0xffffffffu, sum, o);
    if (lane == 0) red[wrp] = sum;
    __syncthreads();
    {
        float v = red[lane];
#pragma unroll
        for (int o = 16; o > 0; o >>= 1) v += __shfl_xor_sync(0xffffffffu, v, o);
        sum = v;
    }
    if (tid == 0) g_ssum[b] = sum;
    const float inv = 1.f / sum;
#pragma unroll
    for (int i = 0; i < 4; ++i) {
        int idx = b*SS + tid + i*1024;
        float a = loc[i] * inv;
        attn_out[idx]   = a;
        covnew_out[idx] = cov[idx] + a;
    }
}

// ============================================================
// K3: reduce ctx partials over 32 chunks and normalize by g_ssum[b].
// ============================================================
__global__ void __launch_bounds__(1024) ctx_reduce_kernel(float* __restrict__ out_ctx)
{
    int i = blockIdx.x * 1024 + threadIdx.x;  // 0..16383 ; b = i>>9
    float s = 0.f;
#pragma unroll
    for (int c = 0; c < CTX_CHUNKS; ++c) s += g_ctx_part[c*(BB*DD) + i];
    out_ctx[i] = s / g_ssum[i >> 9];
}

// ============================================================
extern "C" void kernel_launch(void* const* d_in, const int* in_sizes, int n_in,
                              void* d_out, int out_size)
{
    const float* enc  = (const float*)d_in[0];
    const float* h    = (const float*)d_in[1];
    const float* c    = (const float*)d_in[2];
    const float* mask = (const float*)d_in[3];
    const float* cov  = (const float*)d_in[4];
    const float* Wh   = (const float*)d_in[5];
    const float* Ws   = (const float*)d_in[6];
    const float* Wsb  = (const float*)d_in[7];
    const float* wc   = (const float*)d_in[8];
    const float* vw   = (const float*)d_in[9];

    float* out      = (float*)d_out;
    float* out_ctx  = out;                 // (B,D)   16384
    float* out_attn = out + BB*DD;         // (B,S)   131072
    float* out_cov  = out_attn + BB*SS;    // (B,S)   131072

    cudaFuncSetAttribute(score_f16_kernel,
                         cudaFuncAttributeMaxDynamicSharedMemorySize, SM_TOTAL);

    prep_kernel<<<256, 256>>>(Wh, h, c, Ws, Wsb);
    score_f16_kernel<<<MM/128, 512, SM_TOTAL>>>(enc, cov, wc, vw, mask);
    softmax_kernel<<<BB, 1024>>>(mask, cov, out_attn, out_cov);
    ctx_reduce_kernel<<<(BB*DD)/1024, 1024>>>(out_ctx);
}